// round 16
// baseline (speedup 1.0000x reference)
#include <cuda_runtime.h>
#include <math.h>

// Problem constants
constexpr int kB  = 128;   // batch
constexpr int kT  = 1024;  // time
constexpr int kI  = 128;   // input
constexpr int kH  = 1024;  // hidden
constexpr int kO  = 128;   // output
constexpr int kNG = 4 * kH;          // 4096 gate rows
constexpr int kNCH1 = (kI + kH) / 32;        // 36 chunks (fused, steps >= 1)
constexpr int kNCH0 = (kI + kO + kH) / 32;   // 40 chunks (step 0)
constexpr int kBH = kB * kH;         // 131072

// Scratch (device globals: allocation-free contract)
__device__ float g_Wcs [128 * kNCH1 * 1024];   // fused weights [ci][kc][32 k][32 n]
__device__ float g_Wc0s[128 * kNCH0 * 1024];   // step-0 weights, same layout
__device__ float g_bias0[kNG];
__device__ float g_bias1[kNG];
__device__ float g_Hall[(kT + 1) * kBH];       // h history, slot 0 = h0
__device__ float g_c[kBH];                     // cell state
__device__ unsigned g_arrive;                  // grid barrier state
__device__ unsigned g_release;

__device__ __forceinline__ unsigned long long pack2(float v) {
    unsigned long long r;
    asm("mov.b64 %0, {%1, %1};" : "=l"(r) : "r"(__float_as_uint(v)));
    return r;
}
#define FMA2(acc, a, b) asm("fma.rn.f32x2 %0, %1, %2, %0;" : "+l"(acc) : "l"(a), "l"(b))

// ---------------------------------------------------------------------------
// Prep: build fused weights  Wc = [W_x | W_hh + W_o@W_out],  Wc0 = [W_x|W_o|W_hh]
// in per-CTA chunk layout [ci][kc][kk][n] (n contiguous). Biases likewise.
// grid 512 x 256; CTA cb handles gate rows n = cb*8 .. cb*8+7
// ---------------------------------------------------------------------------
__global__ __launch_bounds__(256) void prep_weights(
    const float* __restrict__ W_ih, const float* __restrict__ W_hh,
    const float* __restrict__ b_ih, const float* __restrict__ b_hh,
    const float* __restrict__ W_out, const float* __restrict__ b_out)
{
    __shared__ float sWo[8][128];             // W_ih[n][128:256] for the 8 rows
    const int cb = blockIdx.x;
    const int tid = threadIdx.x;

    for (int idx = tid; idx < 8 * 128; idx += 256) {
        int r = idx >> 7, j = idx & 127;
        sWo[r][j] = W_ih[(size_t)(cb * 8 + r) * 256 + 128 + j];
    }
    __syncthreads();

    // acc[r][q] = (W_o @ W_out)[n=cb*8+r][k=tid*4+q]
    const int k4 = tid * 4;
    float acc[8][4];
    #pragma unroll
    for (int r = 0; r < 8; r++)
        #pragma unroll
        for (int q = 0; q < 4; q++) acc[r][q] = 0.f;

    for (int j = 0; j < 128; j++) {
        float4 wo = *(const float4*)&W_out[(size_t)j * kH + k4];
        #pragma unroll
        for (int r = 0; r < 8; r++) {
            float s = sWo[r][j];
            acc[r][0] += s * wo.x; acc[r][1] += s * wo.y;
            acc[r][2] += s * wo.z; acc[r][3] += s * wo.w;
        }
    }

    #pragma unroll
    for (int r = 0; r < 8; r++) {
        int n = cb * 8 + r;
        int g = n >> 10, jglob = n & 1023;
        int ci = jglob >> 3, jj = jglob & 7, lr = g * 8 + jj;
        #pragma unroll
        for (int q = 0; q < 4; q++) {
            int k = k4 + q;
            float whh = W_hh[(size_t)n * kH + k];
            // fused recurrent weight (layout [kk][n])
            int kc1 = (kI + k) >> 5, kk1 = (kI + k) & 31;
            g_Wcs[((size_t)(ci * kNCH1 + kc1) * 32 + kk1) * 32 + lr] = whh + acc[r][q];
            // plain W_hh for step 0
            int kc0 = (kI + kO + k) >> 5, kk0 = (kI + kO + k) & 31;
            g_Wc0s[((size_t)(ci * kNCH0 + kc0) * 32 + kk0) * 32 + lr] = whh;
        }
    }

    // W_ih parts: x-part (both layouts) and o-part (step-0 layout only)
    for (int idx = tid; idx < 8 * 256; idx += 256) {
        int r = idx >> 8, kk = idx & 255;
        int n = cb * 8 + r;
        int g = n >> 10, jglob = n & 1023;
        int ci = jglob >> 3, jj = jglob & 7, lr = g * 8 + jj;
        float v = W_ih[(size_t)n * 256 + kk];
        int kc0 = kk >> 5, kkk = kk & 31;
        g_Wc0s[((size_t)(ci * kNCH0 + kc0) * 32 + kkk) * 32 + lr] = v;
        if (kk < 128)
            g_Wcs[((size_t)(ci * kNCH1 + kc0) * 32 + kkk) * 32 + lr] = v;
    }

    if (tid < 8) {
        int n = cb * 8 + tid;
        float bb = b_ih[n] + b_hh[n];
        float s = 0.f;
        for (int j = 0; j < 128; j++) s += sWo[tid][j] * b_out[j];
        g_bias0[n] = bb;        // step 0 (out_t explicit)
        g_bias1[n] = bb + s;    // fused
    }
}

__global__ __launch_bounds__(256) void init_state(
    const float* __restrict__ hn, const float* __restrict__ cn)
{
    int idx = blockIdx.x * 256 + threadIdx.x;
    if (idx < kBH) {
        g_Hall[idx] = hn[idx];  // slot 0 = h0
        g_c[idx]    = cn[idx];
    }
    if (idx == 0) { g_arrive = 0; g_release = 0; }
}

// ---------------------------------------------------------------------------
// Persistent LSTM: 128 CTAs (one per SM, all resident), 256 threads.
// CTA ci owns h-cols [8ci, 8ci+8) -> 32 gate rows (4 gates x 8 cols).
// Fused weights (steps>=1) live smem-resident: 147.5 KB.
// Per step: gates[128b x 32n] = A[128 x 1152] @ W^T, cell update, grid barrier.
// Warp tile: 32b x 16n; thread microtile 4b x 4n (8 f32x2 accumulators).
// ---------------------------------------------------------------------------
constexpr int SM_W = kNCH1 * 1024;                 // 36864 floats
constexpr int SM_A = 32 * 132;                     // 4224 floats per buffer
constexpr int SMEM_FLOATS = SM_W + 2 * SM_A + 32 * 128 + 128;
constexpr int SMEM_BYTES  = SMEM_FLOATS * 4;       // 198144 B

__global__ void __launch_bounds__(256, 1) lstm_persist(
    const float* __restrict__ x, const int* __restrict__ slen,
    const float* __restrict__ out0)
{
    extern __shared__ float sm[];
    float* sW  = sm;                 // resident fused weights / step-0 staging
    float* sA0 = sm + SM_W;
    float* sA1 = sA0 + SM_A;
    float* sG  = sA1 + SM_A;         // [32 n][128 b]
    int*  sLen = (int*)(sG + 32 * 128);

    const int ci  = blockIdx.x;
    const int tid = threadIdx.x;
    const int wid = tid >> 5, l = tid & 31;
    const int b_lane = (wid & 3) * 32 + (l >> 2) * 4;   // 4 batches
    const int n_lane = (wid >> 2) * 16 + (l & 3) * 4;   // 4 gate rows

    if (tid < 128) sLen[tid] = slen[tid];
    __syncthreads();

    // ---- A-chunk loader: 16 floats/thread as 4 float4 ----
    auto loadA = [&](int t, int kc, bool first, float4* rA) {
        const int kbase = kc * 32;
        const float* __restrict__ hprev = g_Hall + (size_t)t * kBH;
        const int hoff = first ? (kI + kO) : kI;
        #pragma unroll
        for (int e = 0; e < 4; e++) {
            int id = e * 256 + tid;
            int b = id >> 3, k0 = kbase + (id & 7) * 4;
            float4 v;
            if (k0 < kI) {
                v = (t < sLen[b]) ? *(const float4*)&x[((size_t)b * kT + t) * kI + k0]
                                  : make_float4(0.f, 0.f, 0.f, 0.f);
            } else if (first && k0 < kI + kO) {
                v = *(const float4*)&out0[b * kO + (k0 - kI)];
            } else {
                v = *(const float4*)&hprev[(size_t)b * kH + (k0 - hoff)];
            }
            rA[e] = v;
        }
    };
    auto storeA = [&](float* sA, const float4* rA) {
        #pragma unroll
        for (int e = 0; e < 4; e++) {
            int id = e * 256 + tid;
            int b = id >> 3, kk = (id & 7) * 4;
            sA[(kk + 0) * 132 + b] = rA[e].x;
            sA[(kk + 1) * 132 + b] = rA[e].y;
            sA[(kk + 2) * 132 + b] = rA[e].z;
            sA[(kk + 3) * 132 + b] = rA[e].w;
        }
    };

    unsigned long long acc[4][2];
    auto zeroAcc = [&]() {
        #pragma unroll
        for (int j = 0; j < 4; j++) { acc[j][0] = 0ull; acc[j][1] = 0ull; }
    };

    auto computeChunk = [&](const float* sA, const float* Wc) {
        #pragma unroll
        for (int k = 0; k < 32; k++) {
            ulonglong2 a = *(const ulonglong2*)&sA[k * 132 + b_lane];
            float4 w = *(const float4*)&Wc[k * 32 + n_lane];
            unsigned long long w0 = pack2(w.x), w1 = pack2(w.y);
            unsigned long long w2 = pack2(w.z), w3 = pack2(w.w);
            FMA2(acc[0][0], a.x, w0); FMA2(acc[0][1], a.y, w0);
            FMA2(acc[1][0], a.x, w1); FMA2(acc[1][1], a.y, w1);
            FMA2(acc[2][0], a.x, w2); FMA2(acc[2][1], a.y, w2);
            FMA2(acc[3][0], a.x, w3); FMA2(acc[3][1], a.y, w3);
        }
    };

    // ---- gates -> cell update -> h write ----
    auto finishStep = [&](int t, const float* __restrict__ bias) {
        #pragma unroll
        for (int j = 0; j < 4; j++) {
            float4 g;
            g.x = __uint_as_float((unsigned)(acc[j][0] & 0xffffffffull));
            g.y = __uint_as_float((unsigned)(acc[j][0] >> 32));
            g.z = __uint_as_float((unsigned)(acc[j][1] & 0xffffffffull));
            g.w = __uint_as_float((unsigned)(acc[j][1] >> 32));
            *(float4*)&sG[(n_lane + j) * 128 + b_lane] = g;
        }
        __syncthreads();
        float* __restrict__ hnew = g_Hall + (size_t)(t + 1) * kBH;
        #pragma unroll
        for (int it = 0; it < 4; it++) {
            int idx = it * 256 + tid;
            int jj = idx >> 7, b = idx & 127;
            int col = ci * 8 + jj;
            float ig = sG[jj * 128 + b]        + bias[col];
            float fg = sG[(8 + jj) * 128 + b]  + bias[kH + col];
            float gg = sG[(16 + jj) * 128 + b] + bias[2 * kH + col];
            float og = sG[(24 + jj) * 128 + b] + bias[3 * kH + col];
            float is = 1.f / (1.f + expf(-ig));
            float fs = 1.f / (1.f + expf(-fg));
            float gt = tanhf(gg);
            float os = 1.f / (1.f + expf(-og));
            size_t sidx = (size_t)b * kH + col;
            float c = fs * g_c[sidx] + is * gt;
            g_c[sidx]  = c;
            hnew[sidx] = os * tanhf(c);
        }
    };

    // ---- grid barrier (all 128 CTAs resident) ----
    auto gridbar = [&](unsigned target) {
        __syncthreads();
        if (tid == 0) {
            unsigned prev;
            asm volatile("atom.acq_rel.gpu.global.add.u32 %0, [%1], 1;"
                         : "=r"(prev) : "l"(&g_arrive) : "memory");
            if (prev + 1 == target * 128u) {
                asm volatile("st.release.gpu.global.b32 [%0], %1;"
                             :: "l"(&g_release), "r"(target) : "memory");
            } else {
                unsigned v;
                do {
                    asm volatile("ld.acquire.gpu.global.b32 %0, [%1];"
                                 : "=r"(v) : "l"(&g_release) : "memory");
                } while (v < target);
            }
        }
        __syncthreads();
    };

    // ================= step 0: stream step-0 weights =================
    zeroAcc();
    {
        float4 rA[4];
        for (int kc = 0; kc < kNCH0; kc++) {
            loadA(0, kc, true, rA);
            float4 rW = *(const float4*)
                &g_Wc0s[(((size_t)ci * kNCH0 + kc) * 32 + (tid >> 3)) * 32 + (tid & 7) * 4];
            __syncthreads();                  // prior compute done reading staging
            storeA(sA0, rA);
            *(float4*)&sW[(tid >> 3) * 32 + (tid & 7) * 4] = rW;
            __syncthreads();
            computeChunk(sA0, sW);
        }
    }
    finishStep(0, g_bias0);
    gridbar(1);

    // ---- load resident fused weights (147.5 KB) ----
    {
        const float* __restrict__ src = g_Wcs + (size_t)ci * SM_W;
        #pragma unroll
        for (int e = 0; e < 36; e++) {
            int id = (e * 256 + tid) * 4;
            *(float4*)&sW[id] = *(const float4*)&src[id];
        }
    }
    __syncthreads();

    // ================= steps 1..1023: resident weights =================
    float4 rA[4];
    for (int t = 1; t < kT; t++) {
        zeroAcc();
        loadA(t, 0, false, rA);
        storeA(sA0, rA);
        __syncthreads();
        #pragma unroll 1
        for (int kc = 0; kc < kNCH1; kc++) {
            float* cur = (kc & 1) ? sA1 : sA0;
            float* nxt = (kc & 1) ? sA0 : sA1;
            if (kc + 1 < kNCH1) loadA(t, kc + 1, false, rA);
            computeChunk(cur, sW + kc * 1024);
            if (kc + 1 < kNCH1) { storeA(nxt, rA); __syncthreads(); }
        }
        finishStep(t, g_bias1);
        gridbar((unsigned)t + 1);
    }
}

// ---------------------------------------------------------------------------
// Final output projection for all timesteps at once (off the serial path):
// y[b,t,:] = mask ? Hall[t+1][b] @ W_out^T + b_out : 0
// grid 1024 (one CTA per t) x 256 threads; tile [128 b x 128 o], K=1024.
// ---------------------------------------------------------------------------
__global__ __launch_bounds__(256) void out_proj(
    const float* __restrict__ W_out, const float* __restrict__ b_out,
    const int* __restrict__ slen, float* __restrict__ y)
{
    __shared__ __align__(16) float sH[32][132];
    __shared__ __align__(16) float sWo[128][36];

    const int t   = blockIdx.x;
    const int tid = threadIdx.x;
    const int bg = tid & 15, og = tid >> 4;
    const int b0 = bg * 8,  o0 = og * 8;
    const float* __restrict__ h = g_Hall + (size_t)(t + 1) * kBH;

    unsigned long long acc[8][4];
    #pragma unroll
    for (int q = 0; q < 8; q++)
        #pragma unroll
        for (int p = 0; p < 4; p++) acc[q][p] = 0ull;

    float rH[16], rW[16];
    auto loadc = [&](int kc) {
        const int kbase = kc * 32;
        #pragma unroll
        for (int e = 0; e < 16; e++) {
            int idx = e * 256 + tid;
            int row = idx >> 5, kk = idx & 31;
            rH[e] = h[(size_t)row * kH + kbase + kk];
            rW[e] = W_out[(size_t)row * kH + kbase + kk];
        }
    };

    loadc(0);
    for (int kc = 0; kc < 32; kc++) {
        #pragma unroll
        for (int e = 0; e < 16; e++) {
            int idx = e * 256 + tid;
            sH [idx & 31][idx >> 5] = rH[e];
            sWo[idx >> 5][idx & 31] = rW[e];
        }
        __syncthreads();
        if (kc + 1 < 32) loadc(kc + 1);

        #pragma unroll 4
        for (int kk = 0; kk < 32; kk++) {
            ulonglong2 aA = *(const ulonglong2*)&sH[kk][b0];
            ulonglong2 aB = *(const ulonglong2*)&sH[kk][b0 + 4];
            #pragma unroll
            for (int q = 0; q < 8; q++) {
                unsigned long long wp = pack2(sWo[o0 + q][kk]);
                FMA2(acc[q][0], aA.x, wp);
                FMA2(acc[q][1], aA.y, wp);
                FMA2(acc[q][2], aB.x, wp);
                FMA2(acc[q][3], aB.y, wp);
            }
        }
        __syncthreads();
    }

    #pragma unroll
    for (int p = 0; p < 4; p++) {
        int b_lo = b0 + 2 * p, b_hi = b_lo + 1;
        bool m_lo = t < slen[b_lo];
        bool m_hi = t < slen[b_hi];
        #pragma unroll
        for (int q = 0; q < 8; q++) {
            int o = o0 + q;
            float bo = b_out[o];
            float lo = __uint_as_float((unsigned)(acc[q][p] & 0xffffffffull));
            float hi = __uint_as_float((unsigned)(acc[q][p] >> 32));
            y[(size_t)b_lo * (kT * kO) + (size_t)t * kO + o] = m_lo ? (lo + bo) : 0.f;
            y[(size_t)b_hi * (kT * kO) + (size_t)t * kO + o] = m_hi ? (hi + bo) : 0.f;
        }
    }
}

// ---------------------------------------------------------------------------
extern "C" void kernel_launch(void* const* d_in, const int* in_sizes, int n_in,
                              void* d_out, int out_size)
{
    const float* x     = (const float*)d_in[0];
    const int*   slen  = (const int*)  d_in[1];
    const float* hn    = (const float*)d_in[2];
    const float* cn    = (const float*)d_in[3];
    const float* out0  = (const float*)d_in[4];
    const float* W_ih  = (const float*)d_in[5];
    const float* W_hh  = (const float*)d_in[6];
    const float* b_ih  = (const float*)d_in[7];
    const float* b_hh  = (const float*)d_in[8];
    const float* W_out = (const float*)d_in[9];
    const float* b_out = (const float*)d_in[10];
    float* y = (float*)d_out;

    cudaFuncSetAttribute(lstm_persist,
                         cudaFuncAttributeMaxDynamicSharedMemorySize, SMEM_BYTES);

    prep_weights<<<512, 256>>>(W_ih, W_hh, b_ih, b_hh, W_out, b_out);
    init_state<<<512, 256>>>(hn, cn);
    lstm_persist<<<128, 256, SMEM_BYTES>>>(x, slen, out0);
    out_proj<<<1024, 256>>>(W_out, b_out, slen, y);
}

// round 17
// speedup vs baseline: 1.0833x; 1.0833x over previous
#include <cuda_runtime.h>
#include <math.h>

// Problem constants
constexpr int kB  = 128;   // batch
constexpr int kT  = 1024;  // time
constexpr int kI  = 128;   // input
constexpr int kH  = 1024;  // hidden
constexpr int kO  = 128;   // output
constexpr int kNG = 4 * kH;          // 4096 gate rows
constexpr int kNCH1 = (kI + kH) / 32;        // 36 chunks (fused, steps >= 1)
constexpr int kNCH0 = (kI + kO + kH) / 32;   // 40 chunks (step 0)
constexpr int kBH = kB * kH;         // 131072

// Scratch (device globals: allocation-free contract)
__device__ float g_Wcs [128 * kNCH1 * 1024];   // fused weights [ci][kc][32 k][32 n]
__device__ float g_Wc0s[128 * kNCH0 * 1024];   // step-0 weights, same layout
__device__ float g_bias0[kNG];
__device__ float g_bias1[kNG];
__device__ float g_Hall[(kT + 1) * kBH];       // h history, slot 0 = h0
__device__ float g_c[kBH];                     // cell state
__device__ unsigned g_arrive;                  // grid barrier state
__device__ unsigned g_release;

__device__ __forceinline__ unsigned long long pack2(float v) {
    unsigned long long r;
    asm("mov.b64 %0, {%1, %1};" : "=l"(r) : "r"(__float_as_uint(v)));
    return r;
}
#define FMA2(acc, a, b) asm("fma.rn.f32x2 %0, %1, %2, %0;" : "+l"(acc) : "l"(a), "l"(b))
#define ADD2(d, a, b)   asm("add.rn.f32x2 %0, %1, %2;" : "=l"(d) : "l"(a), "l"(b))

// ---------------------------------------------------------------------------
// Prep: build fused weights  Wc = [W_x | W_hh + W_o@W_out],  Wc0 = [W_x|W_o|W_hh]
// in per-CTA chunk layout [ci][kc][kk][n] (n contiguous). Biases likewise.
// grid 512 x 256; CTA cb handles gate rows n = cb*8 .. cb*8+7
// ---------------------------------------------------------------------------
__global__ __launch_bounds__(256) void prep_weights(
    const float* __restrict__ W_ih, const float* __restrict__ W_hh,
    const float* __restrict__ b_ih, const float* __restrict__ b_hh,
    const float* __restrict__ W_out, const float* __restrict__ b_out)
{
    __shared__ float sWo[8][128];             // W_ih[n][128:256] for the 8 rows
    const int cb = blockIdx.x;
    const int tid = threadIdx.x;

    for (int idx = tid; idx < 8 * 128; idx += 256) {
        int r = idx >> 7, j = idx & 127;
        sWo[r][j] = W_ih[(size_t)(cb * 8 + r) * 256 + 128 + j];
    }
    __syncthreads();

    // acc[r][q] = (W_o @ W_out)[n=cb*8+r][k=tid*4+q]
    const int k4 = tid * 4;
    float acc[8][4];
    #pragma unroll
    for (int r = 0; r < 8; r++)
        #pragma unroll
        for (int q = 0; q < 4; q++) acc[r][q] = 0.f;

    for (int j = 0; j < 128; j++) {
        float4 wo = *(const float4*)&W_out[(size_t)j * kH + k4];
        #pragma unroll
        for (int r = 0; r < 8; r++) {
            float s = sWo[r][j];
            acc[r][0] += s * wo.x; acc[r][1] += s * wo.y;
            acc[r][2] += s * wo.z; acc[r][3] += s * wo.w;
        }
    }

    #pragma unroll
    for (int r = 0; r < 8; r++) {
        int n = cb * 8 + r;
        int g = n >> 10, jglob = n & 1023;
        int ci = jglob >> 3, jj = jglob & 7, lr = g * 8 + jj;
        #pragma unroll
        for (int q = 0; q < 4; q++) {
            int k = k4 + q;
            float whh = W_hh[(size_t)n * kH + k];
            // fused recurrent weight (layout [kk][n])
            int kc1 = (kI + k) >> 5, kk1 = (kI + k) & 31;
            g_Wcs[((size_t)(ci * kNCH1 + kc1) * 32 + kk1) * 32 + lr] = whh + acc[r][q];
            // plain W_hh for step 0
            int kc0 = (kI + kO + k) >> 5, kk0 = (kI + kO + k) & 31;
            g_Wc0s[((size_t)(ci * kNCH0 + kc0) * 32 + kk0) * 32 + lr] = whh;
        }
    }

    // W_ih parts: x-part (both layouts) and o-part (step-0 layout only)
    for (int idx = tid; idx < 8 * 256; idx += 256) {
        int r = idx >> 8, kk = idx & 255;
        int n = cb * 8 + r;
        int g = n >> 10, jglob = n & 1023;
        int ci = jglob >> 3, jj = jglob & 7, lr = g * 8 + jj;
        float v = W_ih[(size_t)n * 256 + kk];
        int kc0 = kk >> 5, kkk = kk & 31;
        g_Wc0s[((size_t)(ci * kNCH0 + kc0) * 32 + kkk) * 32 + lr] = v;
        if (kk < 128)
            g_Wcs[((size_t)(ci * kNCH1 + kc0) * 32 + kkk) * 32 + lr] = v;
    }

    if (tid < 8) {
        int n = cb * 8 + tid;
        float bb = b_ih[n] + b_hh[n];
        float s = 0.f;
        for (int j = 0; j < 128; j++) s += sWo[tid][j] * b_out[j];
        g_bias0[n] = bb;        // step 0 (out_t explicit)
        g_bias1[n] = bb + s;    // fused
    }
}

__global__ __launch_bounds__(256) void init_state(
    const float* __restrict__ hn, const float* __restrict__ cn)
{
    int idx = blockIdx.x * 256 + threadIdx.x;
    if (idx < kBH) {
        g_Hall[idx] = hn[idx];  // slot 0 = h0
        g_c[idx]    = cn[idx];
    }
    if (idx == 0) { g_arrive = 0; g_release = 0; }
}

// ---------------------------------------------------------------------------
// Persistent LSTM: 128 CTAs (one per SM, all resident), 256 threads.
// CTA ci owns h-cols [8ci, 8ci+8) -> 32 gate rows (4 gates x 8 cols).
// Fused weights (steps>=1) live smem-resident: 147.5 KB.
// Per step: gates[128b x 32n] = A[128 x 1152] @ W^T, cell update, grid barrier.
// 4 k-groups x 64 threads; each group: full 128b x 32n tile, microtile 8b x 8n,
// over k = 4j + g. Group partials reduced via f32x2 adds through smem.
// ---------------------------------------------------------------------------
constexpr int SM_W = kNCH1 * 1024;                 // 36864 floats
constexpr int SM_A = 32 * 132;                     // 4224 floats per buffer
constexpr int SMEM_FLOATS = SM_W + 2 * SM_A + 32 * 128 + 128;
constexpr int SMEM_BYTES  = SMEM_FLOATS * 4;       // 198144 B

__global__ void __launch_bounds__(256, 1) lstm_persist(
    const float* __restrict__ x, const int* __restrict__ slen,
    const float* __restrict__ out0)
{
    extern __shared__ float sm[];
    float* sW  = sm;                 // resident fused weights / step-0 staging
    float* sA0 = sm + SM_W;
    float* sA1 = sA0 + SM_A;
    float* sG  = sA1 + SM_A;         // [32 n][128 b] final gates / 3rd partial
    int*  sLen = (int*)(sG + 32 * 128);

    const int ci  = blockIdx.x;
    const int tid = threadIdx.x;
    const int g    = tid >> 6;       // k-group 0..3
    const int gtid = tid & 63;
    const int b0 = (gtid & 15) * 8;  // 8 batches
    const int n0 = (gtid >> 4) * 8;  // 8 gate rows

    if (tid < 128) sLen[tid] = slen[tid];
    __syncthreads();

    // ---- A-chunk loader: 16 floats/thread as 4 float4 ----
    auto loadA = [&](int t, int kc, bool first, float4* rA) {
        const int kbase = kc * 32;
        const float* __restrict__ hprev = g_Hall + (size_t)t * kBH;
        const int hoff = first ? (kI + kO) : kI;
        #pragma unroll
        for (int e = 0; e < 4; e++) {
            int id = e * 256 + tid;
            int b = id >> 3, k0 = kbase + (id & 7) * 4;
            float4 v;
            if (k0 < kI) {
                v = (t < sLen[b]) ? *(const float4*)&x[((size_t)b * kT + t) * kI + k0]
                                  : make_float4(0.f, 0.f, 0.f, 0.f);
            } else if (first && k0 < kI + kO) {
                v = *(const float4*)&out0[b * kO + (k0 - kI)];
            } else {
                v = *(const float4*)&hprev[(size_t)b * kH + (k0 - hoff)];
            }
            rA[e] = v;
        }
    };
    auto storeA = [&](float* sA, const float4* rA) {
        #pragma unroll
        for (int e = 0; e < 4; e++) {
            int id = e * 256 + tid;
            int b = id >> 3, kk = (id & 7) * 4;
            sA[(kk + 0) * 132 + b] = rA[e].x;
            sA[(kk + 1) * 132 + b] = rA[e].y;
            sA[(kk + 2) * 132 + b] = rA[e].z;
            sA[(kk + 3) * 132 + b] = rA[e].w;
        }
    };

    // 8n x 8b accumulators as f32x2 over batch pairs
    unsigned long long acc[8][4];
    auto zeroAcc = [&]() {
        #pragma unroll
        for (int n = 0; n < 8; n++)
            #pragma unroll
            for (int p = 0; p < 4; p++) acc[n][p] = 0ull;
    };

    // this group's 8 k-values of the staged 32-k chunk: k = 4j + g
    auto computeChunk = [&](const float* sA, const float* Wc) {
        #pragma unroll
        for (int j = 0; j < 8; j++) {
            const int k = j * 4 + g;
            ulonglong2 a01 = *(const ulonglong2*)&sA[k * 132 + b0];
            ulonglong2 a23 = *(const ulonglong2*)&sA[k * 132 + b0 + 4];
            float4 wlo = *(const float4*)&Wc[k * 32 + n0];
            float4 whi = *(const float4*)&Wc[k * 32 + n0 + 4];
            unsigned long long wp;
            wp = pack2(wlo.x);
            FMA2(acc[0][0], a01.x, wp); FMA2(acc[0][1], a01.y, wp);
            FMA2(acc[0][2], a23.x, wp); FMA2(acc[0][3], a23.y, wp);
            wp = pack2(wlo.y);
            FMA2(acc[1][0], a01.x, wp); FMA2(acc[1][1], a01.y, wp);
            FMA2(acc[1][2], a23.x, wp); FMA2(acc[1][3], a23.y, wp);
            wp = pack2(wlo.z);
            FMA2(acc[2][0], a01.x, wp); FMA2(acc[2][1], a01.y, wp);
            FMA2(acc[2][2], a23.x, wp); FMA2(acc[2][3], a23.y, wp);
            wp = pack2(wlo.w);
            FMA2(acc[3][0], a01.x, wp); FMA2(acc[3][1], a01.y, wp);
            FMA2(acc[3][2], a23.x, wp); FMA2(acc[3][3], a23.y, wp);
            wp = pack2(whi.x);
            FMA2(acc[4][0], a01.x, wp); FMA2(acc[4][1], a01.y, wp);
            FMA2(acc[4][2], a23.x, wp); FMA2(acc[4][3], a23.y, wp);
            wp = pack2(whi.y);
            FMA2(acc[5][0], a01.x, wp); FMA2(acc[5][1], a01.y, wp);
            FMA2(acc[5][2], a23.x, wp); FMA2(acc[5][3], a23.y, wp);
            wp = pack2(whi.z);
            FMA2(acc[6][0], a01.x, wp); FMA2(acc[6][1], a01.y, wp);
            FMA2(acc[6][2], a23.x, wp); FMA2(acc[6][3], a23.y, wp);
            wp = pack2(whi.w);
            FMA2(acc[7][0], a01.x, wp); FMA2(acc[7][1], a01.y, wp);
            FMA2(acc[7][2], a23.x, wp); FMA2(acc[7][3], a23.y, wp);
        }
    };

    auto writePartial = [&](float* P) {
        #pragma unroll
        for (int n = 0; n < 8; n++) {
            ulonglong2 v0; v0.x = acc[n][0]; v0.y = acc[n][1];
            ulonglong2 v1; v1.x = acc[n][2]; v1.y = acc[n][3];
            *(ulonglong2*)&P[(n0 + n) * 128 + b0]     = v0;
            *(ulonglong2*)&P[(n0 + n) * 128 + b0 + 4] = v1;
        }
    };
    auto addPartial = [&](const float* P) {
        #pragma unroll
        for (int n = 0; n < 8; n++) {
            ulonglong2 v0 = *(const ulonglong2*)&P[(n0 + n) * 128 + b0];
            ulonglong2 v1 = *(const ulonglong2*)&P[(n0 + n) * 128 + b0 + 4];
            ADD2(acc[n][0], acc[n][0], v0.x);
            ADD2(acc[n][1], acc[n][1], v0.y);
            ADD2(acc[n][2], acc[n][2], v1.x);
            ADD2(acc[n][3], acc[n][3], v1.y);
        }
    };

    // reduce the 4 group partials into sG (g1->sA0, g2->sA1, g3->sG, g0 sums)
    auto reduceGroups = [&]() {
        __syncthreads();                 // all k reads done; A buffers now free
        if (g == 1) writePartial(sA0);
        else if (g == 2) writePartial(sA1);
        else if (g == 3) writePartial(sG);
        __syncthreads();
        if (g == 0) {
            addPartial(sA0);
            addPartial(sA1);
            addPartial(sG);
            writePartial(sG);            // final gates
        }
        __syncthreads();
    };

    // ---- gates -> cell update -> h write ----
    auto finishStep = [&](int t, const float* __restrict__ bias) {
        float* __restrict__ hnew = g_Hall + (size_t)(t + 1) * kBH;
        #pragma unroll
        for (int it = 0; it < 4; it++) {
            int idx = it * 256 + tid;
            int jj = idx >> 7, b = idx & 127;
            int col = ci * 8 + jj;
            float ig = sG[jj * 128 + b]        + bias[col];
            float fg = sG[(8 + jj) * 128 + b]  + bias[kH + col];
            float gg = sG[(16 + jj) * 128 + b] + bias[2 * kH + col];
            float og = sG[(24 + jj) * 128 + b] + bias[3 * kH + col];
            float is = 1.f / (1.f + expf(-ig));
            float fs = 1.f / (1.f + expf(-fg));
            float gt = tanhf(gg);
            float os = 1.f / (1.f + expf(-og));
            size_t sidx = (size_t)b * kH + col;
            float c = fs * g_c[sidx] + is * gt;
            g_c[sidx]  = c;
            hnew[sidx] = os * tanhf(c);
        }
    };

    // ---- grid barrier (all 128 CTAs resident) ----
    auto gridbar = [&](unsigned target) {
        __syncthreads();
        if (tid == 0) {
            unsigned prev;
            asm volatile("atom.acq_rel.gpu.global.add.u32 %0, [%1], 1;"
                         : "=r"(prev) : "l"(&g_arrive) : "memory");
            if (prev + 1 == target * 128u) {
                asm volatile("st.release.gpu.global.b32 [%0], %1;"
                             :: "l"(&g_release), "r"(target) : "memory");
            } else {
                unsigned v;
                do {
                    asm volatile("ld.acquire.gpu.global.b32 %0, [%1];"
                                 : "=r"(v) : "l"(&g_release) : "memory");
                } while (v < target);
            }
        }
        __syncthreads();
    };

    // ================= step 0: stream step-0 weights =================
    zeroAcc();
    {
        float4 rA[4];
        for (int kc = 0; kc < kNCH0; kc++) {
            loadA(0, kc, true, rA);
            float4 rW = *(const float4*)
                &g_Wc0s[(((size_t)ci * kNCH0 + kc) * 32 + (tid >> 3)) * 32 + (tid & 7) * 4];
            __syncthreads();                  // prior compute done reading staging
            storeA(sA0, rA);
            *(float4*)&sW[(tid >> 3) * 32 + (tid & 7) * 4] = rW;
            __syncthreads();
            computeChunk(sA0, sW);
        }
    }
    reduceGroups();
    finishStep(0, g_bias0);
    gridbar(1);

    // ---- load resident fused weights (147.5 KB) ----
    {
        const float* __restrict__ src = g_Wcs + (size_t)ci * SM_W;
        #pragma unroll
        for (int e = 0; e < 36; e++) {
            int id = (e * 256 + tid) * 4;
            *(float4*)&sW[id] = *(const float4*)&src[id];
        }
    }
    __syncthreads();

    // ================= steps 1..1023: resident weights =================
    float4 rA[4];
    for (int t = 1; t < kT; t++) {
        zeroAcc();
        loadA(t, 0, false, rA);
        storeA(sA0, rA);
        __syncthreads();
        #pragma unroll 1
        for (int kc = 0; kc < kNCH1; kc++) {
            float* cur = (kc & 1) ? sA1 : sA0;
            float* nxt = (kc & 1) ? sA0 : sA1;
            if (kc + 1 < kNCH1) loadA(t, kc + 1, false, rA);
            computeChunk(cur, sW + kc * 1024);
            if (kc + 1 < kNCH1) { storeA(nxt, rA); __syncthreads(); }
        }
        reduceGroups();
        finishStep(t, g_bias1);
        gridbar((unsigned)t + 1);
    }
}

// ---------------------------------------------------------------------------
// Final output projection for all timesteps at once (off the serial path):
// y[b,t,:] = mask ? Hall[t+1][b] @ W_out^T + b_out : 0
// grid 1024 (one CTA per t) x 256 threads; tile [128 b x 128 o], K=1024.
// ---------------------------------------------------------------------------
__global__ __launch_bounds__(256) void out_proj(
    const float* __restrict__ W_out, const float* __restrict__ b_out,
    const int* __restrict__ slen, float* __restrict__ y)
{
    __shared__ __align__(16) float sH[32][132];
    __shared__ __align__(16) float sWo[128][36];

    const int t   = blockIdx.x;
    const int tid = threadIdx.x;
    const int bg = tid & 15, og = tid >> 4;
    const int b0 = bg * 8,  o0 = og * 8;
    const float* __restrict__ h = g_Hall + (size_t)(t + 1) * kBH;

    unsigned long long acc[8][4];
    #pragma unroll
    for (int q = 0; q < 8; q++)
        #pragma unroll
        for (int p = 0; p < 4; p++) acc[q][p] = 0ull;

    float rH[16], rW[16];
    auto loadc = [&](int kc) {
        const int kbase = kc * 32;
        #pragma unroll
        for (int e = 0; e < 16; e++) {
            int idx = e * 256 + tid;
            int row = idx >> 5, kk = idx & 31;
            rH[e] = h[(size_t)row * kH + kbase + kk];
            rW[e] = W_out[(size_t)row * kH + kbase + kk];
        }
    };

    loadc(0);
    for (int kc = 0; kc < 32; kc++) {
        #pragma unroll
        for (int e = 0; e < 16; e++) {
            int idx = e * 256 + tid;
            sH [idx & 31][idx >> 5] = rH[e];
            sWo[idx >> 5][idx & 31] = rW[e];
        }
        __syncthreads();
        if (kc + 1 < 32) loadc(kc + 1);

        #pragma unroll 4
        for (int kk = 0; kk < 32; kk++) {
            ulonglong2 aA = *(const ulonglong2*)&sH[kk][b0];
            ulonglong2 aB = *(const ulonglong2*)&sH[kk][b0 + 4];
            #pragma unroll
            for (int q = 0; q < 8; q++) {
                unsigned long long wp = pack2(sWo[o0 + q][kk]);
                FMA2(acc[q][0], aA.x, wp);
                FMA2(acc[q][1], aA.y, wp);
                FMA2(acc[q][2], aB.x, wp);
                FMA2(acc[q][3], aB.y, wp);
            }
        }
        __syncthreads();
    }

    #pragma unroll
    for (int p = 0; p < 4; p++) {
        int b_lo = b0 + 2 * p, b_hi = b_lo + 1;
        bool m_lo = t < slen[b_lo];
        bool m_hi = t < slen[b_hi];
        #pragma unroll
        for (int q = 0; q < 8; q++) {
            int o = o0 + q;
            float bo = b_out[o];
            float lo = __uint_as_float((unsigned)(acc[q][p] & 0xffffffffull));
            float hi = __uint_as_float((unsigned)(acc[q][p] >> 32));
            y[(size_t)b_lo * (kT * kO) + (size_t)t * kO + o] = m_lo ? (lo + bo) : 0.f;
            y[(size_t)b_hi * (kT * kO) + (size_t)t * kO + o] = m_hi ? (hi + bo) : 0.f;
        }
    }
}

// ---------------------------------------------------------------------------
extern "C" void kernel_launch(void* const* d_in, const int* in_sizes, int n_in,
                              void* d_out, int out_size)
{
    const float* x     = (const float*)d_in[0];
    const int*   slen  = (const int*)  d_in[1];
    const float* hn    = (const float*)d_in[2];
    const float* cn    = (const float*)d_in[3];
    const float* out0  = (const float*)d_in[4];
    const float* W_ih  = (const float*)d_in[5];
    const float* W_hh  = (const float*)d_in[6];
    const float* b_ih  = (const float*)d_in[7];
    const float* b_hh  = (const float*)d_in[8];
    const float* W_out = (const float*)d_in[9];
    const float* b_out = (const float*)d_in[10];
    float* y = (float*)d_out;

    cudaFuncSetAttribute(lstm_persist,
                         cudaFuncAttributeMaxDynamicSharedMemorySize, SMEM_BYTES);

    prep_weights<<<512, 256>>>(W_ih, W_hh, b_ih, b_hh, W_out, b_out);
    init_state<<<512, 256>>>(hn, cn);
    lstm_persist<<<128, 256, SMEM_BYTES>>>(x, slen, out0);
    out_proj<<<1024, 256>>>(W_out, b_out, slen, y);
}